// round 5
// baseline (speedup 1.0000x reference)
#include <cuda_runtime.h>

#define NUM_MODELS 64
#define IN_F 6
#define HID 64
#define OUT_F 3
#define B_MAX 131072
#define K_CHUNKS 8
#define TPB_MLP 128

// -------- scratch (no allocations allowed; __device__ globals) --------
__device__ int g_counts[NUM_MODELS];
__device__ int g_offsets[NUM_MODELS];
__device__ int g_cursor[NUM_MODELS];
__device__ int g_rowids[B_MAX];
__device__ unsigned char g_idx[B_MAX];

// -------- smem layout for one model's weights (floats) --------
#define SW0 0                    // 64*6
#define SB0 (SW0 + 384)          // 64
#define SW1 (SB0 + 64)           // 64*64
#define SB1 (SW1 + 4096)         // 64
#define SW2 (SB1 + 64)           // 64*64
#define SB2 (SW2 + 4096)         // 64
#define SW3 (SB2 + 64)           // 64*64
#define SB3 (SW3 + 4096)         // 64
#define SW4 (SB3 + 64)           // 3*64
#define SB4 (SW4 + 192)          // 3 (+1 pad)
#define SMEM_FLOATS (SB4 + 4)
#define SMEM_BYTES (SMEM_FLOATS * 4)

__device__ __forceinline__ float2 ffma2(float2 a, float2 b, float2 c) {
    float2 d;
    asm("fma.rn.f32x2 %0, %1, %2, %3;"
        : "=l"(reinterpret_cast<unsigned long long&>(d))
        : "l"(reinterpret_cast<const unsigned long long&>(a)),
          "l"(reinterpret_cast<const unsigned long long&>(b)),
          "l"(reinterpret_cast<const unsigned long long&>(c)));
    return d;
}

// ---------------------------------------------------------------------
// Kernel 1: zero histogram + fill constant outputs (logits=1, probs=1/64)
// ---------------------------------------------------------------------
__global__ void k_fill(float* __restrict__ out_logits,
                       float* __restrict__ out_probs, int n4) {
    if (blockIdx.x == 0 && threadIdx.x < NUM_MODELS)
        g_counts[threadIdx.x] = 0;
    int gid = blockIdx.x * blockDim.x + threadIdx.x;
    int stride = gridDim.x * blockDim.x;
    float4 ones = make_float4(1.f, 1.f, 1.f, 1.f);
    float4 prob = make_float4(0.015625f, 0.015625f, 0.015625f, 0.015625f);
    float4* L = (float4*)out_logits;
    float4* P = (float4*)out_probs;
    for (int i = gid; i < n4; i += stride) {
        L[i] = ones;
        P[i] = prob;
    }
}

// ---------------------------------------------------------------------
// Kernel 2: selection index per row + histogram.
// Correctly-rounded intrinsics: result identical with or without
// fast-math; libdevice atan2f/fmodf match XLA's lowering bitwise.
// ---------------------------------------------------------------------
__global__ void k_index(const float* __restrict__ in,
                        float* __restrict__ out_idx, int B) {
    const float TWO_PI = 6.28318530717958647692f;
    int gid = blockIdx.x * blockDim.x + threadIdx.x;
    int stride = gridDim.x * blockDim.x;
    for (int r = gid; r < B; r += stride) {
        float x0 = in[6 * r + 0];
        float x2 = in[6 * r + 2];
        float ang = atan2f(x2, x0);
        float a = fmodf(__fadd_rn(ang, TWO_PI), TWO_PI);  // positive args: mod==fmod
        a = __fmul_rn(__fdiv_rn(a, TWO_PI), 64.0f);
        float f = floorf(a);
        int idx = (int)f;
        int idxw = idx > 63 ? 63 : (idx < 0 ? 0 : idx);   // XLA gather clamps OOB
        g_idx[r] = (unsigned char)idxw;
        out_idx[r] = f;                                   // selection_indices (as f32)
        atomicAdd(&g_counts[idxw], 1);
    }
}

// ---------------------------------------------------------------------
// Kernel 3: exclusive scan (64 entries; trivial serial)
// ---------------------------------------------------------------------
__global__ void k_scan() {
    if (threadIdx.x == 0) {
        int run = 0;
        for (int m = 0; m < NUM_MODELS; m++) {
            g_offsets[m] = run;
            g_cursor[m] = run;
            run += g_counts[m];
        }
    }
}

// ---------------------------------------------------------------------
// Kernel 4: scatter row ids into per-model buckets
// ---------------------------------------------------------------------
__global__ void k_scatter(int B) {
    int gid = blockIdx.x * blockDim.x + threadIdx.x;
    int stride = gridDim.x * blockDim.x;
    for (int r = gid; r < B; r += stride) {
        int m = g_idx[r];
        int pos = atomicAdd(&g_cursor[m], 1);
        g_rowids[pos] = r;
    }
}

// ---------------------------------------------------------------------
// helpers for k_mlp
// ---------------------------------------------------------------------
__device__ __forceinline__ void cpyf4(float* dst, const float* src, int nf4) {
    const float4* s4 = (const float4*)src;
    float4* d4 = (float4*)dst;
    for (int i = threadIdx.x; i < nf4; i += TPB_MLP) d4[i] = s4[i];
}

// one 64x64 dense layer + relu; weights broadcast from smem, f32x2 packed.
// 4 independent accumulator chains -> enough ILP to cover fma lat=4 at
// rt_SMSP=2 even at low warp count.
__device__ __forceinline__ void dense64(const float* __restrict__ w,
                                        const float* __restrict__ b,
                                        float2 h[32]) {
    float2 hn[32];
#pragma unroll
    for (int o = 0; o < 64; o += 2) {
        const float4* w0q = (const float4*)(w + o * 64);
        const float4* w1q = (const float4*)(w + (o + 1) * 64);
        float2 a0 = make_float2(0.f, 0.f), c0 = a0, a1 = a0, c1 = a0;
#pragma unroll
        for (int i4 = 0; i4 < 16; i4++) {
            float4 q0 = w0q[i4];
            float4 q1 = w1q[i4];
            a0 = ffma2(make_float2(q0.x, q0.y), h[2 * i4], a0);
            c0 = ffma2(make_float2(q0.z, q0.w), h[2 * i4 + 1], c0);
            a1 = ffma2(make_float2(q1.x, q1.y), h[2 * i4], a1);
            c1 = ffma2(make_float2(q1.z, q1.w), h[2 * i4 + 1], c1);
        }
        float v0 = b[o] + (a0.x + a0.y) + (c0.x + c0.y);
        float v1 = b[o + 1] + (a1.x + a1.y) + (c1.x + c1.y);
        hn[o >> 1] = make_float2(fmaxf(v0, 0.f), fmaxf(v1, 0.f));
    }
#pragma unroll
    for (int i = 0; i < 32; i++) h[i] = hn[i];
}

// ---------------------------------------------------------------------
// Kernel 5: bucketed MLP. blockIdx.x -> (model, chunk). One model per CTA,
// full 52.5KB weight set in dynamic smem, rows of that model per-thread.
// Grid 512 CTAs @ 4 CTAs/SM (smem limit) = single wave on 148 SMs.
// ---------------------------------------------------------------------
__global__ void __launch_bounds__(TPB_MLP, 3)
k_mlp(const float* __restrict__ inputs,
      const float* __restrict__ w0, const float* __restrict__ b0,
      const float* __restrict__ w1, const float* __restrict__ b1,
      const float* __restrict__ w2, const float* __restrict__ b2,
      const float* __restrict__ w3, const float* __restrict__ b3,
      const float* __restrict__ w4, const float* __restrict__ b4,
      float* __restrict__ out_model, float* __restrict__ out_top) {
    extern __shared__ float s[];
    int m = blockIdx.x / K_CHUNKS;
    int chunk = blockIdx.x % K_CHUNKS;

    // cooperative weight load (all per-model slices are 16B-aligned)
    cpyf4(s + SW0, w0 + m * 384, 384 / 4);
    cpyf4(s + SB0, b0 + m * 64, 16);
    cpyf4(s + SW1, w1 + m * 4096, 1024);
    cpyf4(s + SB1, b1 + m * 64, 16);
    cpyf4(s + SW2, w2 + m * 4096, 1024);
    cpyf4(s + SB2, b2 + m * 64, 16);
    cpyf4(s + SW3, w3 + m * 4096, 1024);
    cpyf4(s + SB3, b3 + m * 64, 16);
    cpyf4(s + SW4, w4 + m * 192, 48);
    if (threadIdx.x < OUT_F) s[SB4 + threadIdx.x] = b4[m * 3 + threadIdx.x];
    __syncthreads();

    int count = g_counts[m];
    int off = g_offsets[m];

    for (int base = chunk * TPB_MLP; base < count; base += K_CHUNKS * TPB_MLP) {
        int j = base + (int)threadIdx.x;
        if (j < count) {
            int r = g_rowids[off + j];
            float x6[IN_F];
#pragma unroll
            for (int k = 0; k < IN_F; k++) x6[k] = inputs[6 * r + k];

            // layer 0: 6 -> 64 (+relu)
            float2 h[32];
#pragma unroll
            for (int o = 0; o < 64; o += 2) {
                float acc0 = s[SB0 + o];
                float acc1 = s[SB0 + o + 1];
#pragma unroll
                for (int i = 0; i < IN_F; i++) {
                    acc0 = fmaf(s[SW0 + o * 6 + i], x6[i], acc0);
                    acc1 = fmaf(s[SW0 + (o + 1) * 6 + i], x6[i], acc1);
                }
                h[o >> 1] = make_float2(fmaxf(acc0, 0.f), fmaxf(acc1, 0.f));
            }

            // layers 1-3: 64 -> 64 (+relu)
            dense64(s + SW1, s + SB1, h);
            dense64(s + SW2, s + SB2, h);
            dense64(s + SW3, s + SB3, h);

            // layer 4: 64 -> 3 (no relu)
            float o3[OUT_F];
#pragma unroll
            for (int o = 0; o < OUT_F; o++) {
                const float4* wq = (const float4*)(s + SW4 + o * 64);
                float2 a = make_float2(0.f, 0.f), c = a;
#pragma unroll
                for (int i4 = 0; i4 < 16; i4++) {
                    float4 q = wq[i4];
                    a = ffma2(make_float2(q.x, q.y), h[2 * i4], a);
                    c = ffma2(make_float2(q.z, q.w), h[2 * i4 + 1], c);
                }
                o3[o] = s[SB4 + o] + (a.x + a.y) + (c.x + c.y);
            }
#pragma unroll
            for (int o = 0; o < OUT_F; o++) {
                out_model[3 * r + o] = o3[o];
                out_top[3 * r + o] = o3[o];
            }
        }
    }
}

// ---------------------------------------------------------------------
extern "C" void kernel_launch(void* const* d_in, const int* in_sizes, int n_in,
                              void* d_out, int out_size) {
    const float* inputs = (const float*)d_in[0];
    const float* w0 = (const float*)d_in[1];
    const float* b0 = (const float*)d_in[2];
    const float* w1 = (const float*)d_in[3];
    const float* b1 = (const float*)d_in[4];
    const float* w2 = (const float*)d_in[5];
    const float* b2 = (const float*)d_in[6];
    const float* w3 = (const float*)d_in[7];
    const float* b3 = (const float*)d_in[8];
    const float* w4 = (const float*)d_in[9];
    const float* b4 = (const float*)d_in[10];

    int B = in_sizes[0] / IN_F;
    if (B > B_MAX) B = B_MAX;
    float* out = (float*)d_out;

    // output layout: model(3B) | top(3B) | idx(B) | logits(64B) | probs(64B)
    size_t Bs = (size_t)B;
    float* out_model = out;
    float* out_top = out + 3 * Bs;
    float* out_idx = out + 6 * Bs;
    float* out_logits = out + 7 * Bs;
    float* out_probs = out + 71 * Bs;

    cudaFuncSetAttribute(k_mlp, cudaFuncAttributeMaxDynamicSharedMemorySize,
                         SMEM_BYTES);

    k_fill<<<1024, 256>>>(out_logits, out_probs, B * 16);
    k_index<<<512, 256>>>(inputs, out_idx, B);
    k_scan<<<1, 32>>>();
    k_scatter<<<512, 256>>>(B);
    k_mlp<<<NUM_MODELS * K_CHUNKS, TPB_MLP, SMEM_BYTES>>>(
        inputs, w0, b0, w1, b1, w2, b2, w3, b3, w4, b4, out_model, out_top);
}

// round 6
// speedup vs baseline: 1.3164x; 1.3164x over previous
#include <cuda_runtime.h>

#define NUM_MODELS 64
#define IN_F 6
#define HID 64
#define OUT_F 3
#define B_MAX 131072
#define K_CHUNKS 4
#define TPB_MLP 128

// -------- scratch (no allocations allowed; __device__ globals) --------
__device__ int g_counts[NUM_MODELS];
__device__ int g_offsets[NUM_MODELS];
__device__ int g_cursor[NUM_MODELS];
__device__ int g_rowids[B_MAX];
__device__ unsigned char g_idx[B_MAX];

// -------- smem layout for one model's weights (floats) --------
#define SW0 0                    // 64*6
#define SB0 (SW0 + 384)          // 64
#define SW1 (SB0 + 64)           // 64*64
#define SB1 (SW1 + 4096)         // 64
#define SW2 (SB1 + 64)           // 64*64
#define SB2 (SW2 + 4096)         // 64
#define SW3 (SB2 + 64)           // 64*64
#define SB3 (SW3 + 4096)         // 64
#define SW4 (SB3 + 64)           // 3*64
#define SB4 (SW4 + 192)          // 3 (+1 pad)
#define SMEM_FLOATS (SB4 + 4)
#define SMEM_BYTES (SMEM_FLOATS * 4)

__device__ __forceinline__ float2 ffma2(float2 a, float2 b, float2 c) {
    float2 d;
    asm("fma.rn.f32x2 %0, %1, %2, %3;"
        : "=l"(reinterpret_cast<unsigned long long&>(d))
        : "l"(reinterpret_cast<const unsigned long long&>(a)),
          "l"(reinterpret_cast<const unsigned long long&>(b)),
          "l"(reinterpret_cast<const unsigned long long&>(c)));
    return d;
}

// ---------------------------------------------------------------------
// Kernel 1: zero histogram + fill constant outputs (logits=1, probs=1/64)
// ---------------------------------------------------------------------
__global__ void k_fill(float* __restrict__ out_logits,
                       float* __restrict__ out_probs, int n4) {
    if (blockIdx.x == 0 && threadIdx.x < NUM_MODELS)
        g_counts[threadIdx.x] = 0;
    int gid = blockIdx.x * blockDim.x + threadIdx.x;
    int stride = gridDim.x * blockDim.x;
    float4 ones = make_float4(1.f, 1.f, 1.f, 1.f);
    float4 prob = make_float4(0.015625f, 0.015625f, 0.015625f, 0.015625f);
    float4* L = (float4*)out_logits;
    float4* P = (float4*)out_probs;
    for (int i = gid; i < n4; i += stride) {
        L[i] = ones;
        P[i] = prob;
    }
}

// ---------------------------------------------------------------------
// Kernel 2: selection index per row. SMEM histogram per CTA -> one global
// atomic per (CTA, model): global atomics 131072 -> 16384 (was the 37us
// serialization hot spot, issue=0.7% in ncu).
// ---------------------------------------------------------------------
__global__ void k_index(const float* __restrict__ in,
                        float* __restrict__ out_idx, int B) {
    __shared__ int hist[NUM_MODELS];
    if (threadIdx.x < NUM_MODELS) hist[threadIdx.x] = 0;
    __syncthreads();

    const float TWO_PI = 6.28318530717958647692f;
    int gid = blockIdx.x * blockDim.x + threadIdx.x;
    int stride = gridDim.x * blockDim.x;
    for (int r = gid; r < B; r += stride) {
        float x0 = in[6 * r + 0];
        float x2 = in[6 * r + 2];
        float ang = atan2f(x2, x0);
        float a = fmodf(__fadd_rn(ang, TWO_PI), TWO_PI);  // positive args: mod==fmod
        a = __fmul_rn(__fdiv_rn(a, TWO_PI), 64.0f);
        float f = floorf(a);
        int idx = (int)f;
        int idxw = idx > 63 ? 63 : (idx < 0 ? 0 : idx);   // XLA gather clamps OOB
        g_idx[r] = (unsigned char)idxw;
        out_idx[r] = f;                                   // selection_indices (as f32)
        atomicAdd(&hist[idxw], 1);
    }
    __syncthreads();
    if (threadIdx.x < NUM_MODELS) {
        int c = hist[threadIdx.x];
        if (c) atomicAdd(&g_counts[threadIdx.x], c);
    }
}

// ---------------------------------------------------------------------
// Kernel 3: exclusive scan (64 entries; trivial serial)
// ---------------------------------------------------------------------
__global__ void k_scan() {
    if (threadIdx.x == 0) {
        int run = 0;
        for (int m = 0; m < NUM_MODELS; m++) {
            g_offsets[m] = run;
            g_cursor[m] = run;
            run += g_counts[m];
        }
    }
}

// ---------------------------------------------------------------------
// Kernel 4: scatter row ids into per-model buckets. Two-pass per CTA over a
// contiguous row range: SMEM count -> reserve global range (1 atomic per
// model per CTA) -> SMEM-cursor scatter. Bucket-internal order is arbitrary.
// ---------------------------------------------------------------------
__global__ void k_scatter(int B) {
    __shared__ int hist[NUM_MODELS];
    __shared__ int base[NUM_MODELS];
    int per = (B + gridDim.x - 1) / gridDim.x;
    int r0 = blockIdx.x * per;
    int r1 = r0 + per;
    if (r1 > B) r1 = B;

    if (threadIdx.x < NUM_MODELS) hist[threadIdx.x] = 0;
    __syncthreads();
    for (int r = r0 + threadIdx.x; r < r1; r += blockDim.x)
        atomicAdd(&hist[g_idx[r]], 1);
    __syncthreads();
    if (threadIdx.x < NUM_MODELS) {
        int c = hist[threadIdx.x];
        base[threadIdx.x] = c ? atomicAdd(&g_cursor[threadIdx.x], c) : 0;
        hist[threadIdx.x] = 0;
    }
    __syncthreads();
    for (int r = r0 + threadIdx.x; r < r1; r += blockDim.x) {
        int m = g_idx[r];
        int p = base[m] + atomicAdd(&hist[m], 1);
        g_rowids[p] = r;
    }
}

// ---------------------------------------------------------------------
// helpers for k_mlp
// ---------------------------------------------------------------------
__device__ __forceinline__ void cpyf4(float* dst, const float* src, int nf4) {
    const float4* s4 = (const float4*)src;
    float4* d4 = (float4*)dst;
    for (int i = threadIdx.x; i < nf4; i += TPB_MLP) d4[i] = s4[i];
}

// one 64x64 dense layer + relu; weights broadcast from smem, f32x2 packed.
// 4 independent accumulator chains cover fma lat=4 @ rt=2 at 2 warps/SMSP.
__device__ __forceinline__ void dense64(const float* __restrict__ w,
                                        const float* __restrict__ b,
                                        float2 h[32]) {
    float2 hn[32];
#pragma unroll
    for (int o = 0; o < 64; o += 2) {
        const float4* w0q = (const float4*)(w + o * 64);
        const float4* w1q = (const float4*)(w + (o + 1) * 64);
        float2 a0 = make_float2(0.f, 0.f), c0 = a0, a1 = a0, c1 = a0;
#pragma unroll
        for (int i4 = 0; i4 < 16; i4++) {
            float4 q0 = w0q[i4];
            float4 q1 = w1q[i4];
            a0 = ffma2(make_float2(q0.x, q0.y), h[2 * i4], a0);
            c0 = ffma2(make_float2(q0.z, q0.w), h[2 * i4 + 1], c0);
            a1 = ffma2(make_float2(q1.x, q1.y), h[2 * i4], a1);
            c1 = ffma2(make_float2(q1.z, q1.w), h[2 * i4 + 1], c1);
        }
        float v0 = b[o] + (a0.x + a0.y) + (c0.x + c0.y);
        float v1 = b[o + 1] + (a1.x + a1.y) + (c1.x + c1.y);
        hn[o >> 1] = make_float2(fmaxf(v0, 0.f), fmaxf(v1, 0.f));
    }
#pragma unroll
    for (int i = 0; i < 32; i++) h[i] = hn[i];
}

// ---------------------------------------------------------------------
// Kernel 5: bucketed MLP. blockIdx.x -> (model, chunk). One model per CTA,
// full 52.5KB weight set in dynamic smem, rows of that model per-thread.
// No reg cap (needs ~160 for h+hn double buffer; the old (128,3) bound
// forced spills). Grid 256 @ 2-3 CTAs/SM = single wave.
// ---------------------------------------------------------------------
__global__ void __launch_bounds__(TPB_MLP)
k_mlp(const float* __restrict__ inputs,
      const float* __restrict__ w0, const float* __restrict__ b0,
      const float* __restrict__ w1, const float* __restrict__ b1,
      const float* __restrict__ w2, const float* __restrict__ b2,
      const float* __restrict__ w3, const float* __restrict__ b3,
      const float* __restrict__ w4, const float* __restrict__ b4,
      float* __restrict__ out_model, float* __restrict__ out_top) {
    extern __shared__ float s[];
    int m = blockIdx.x / K_CHUNKS;
    int chunk = blockIdx.x % K_CHUNKS;

    // cooperative weight load (all per-model slices are 16B-aligned)
    cpyf4(s + SW0, w0 + m * 384, 384 / 4);
    cpyf4(s + SB0, b0 + m * 64, 16);
    cpyf4(s + SW1, w1 + m * 4096, 1024);
    cpyf4(s + SB1, b1 + m * 64, 16);
    cpyf4(s + SW2, w2 + m * 4096, 1024);
    cpyf4(s + SB2, b2 + m * 64, 16);
    cpyf4(s + SW3, w3 + m * 4096, 1024);
    cpyf4(s + SB3, b3 + m * 64, 16);
    cpyf4(s + SW4, w4 + m * 192, 48);
    if (threadIdx.x < OUT_F) s[SB4 + threadIdx.x] = b4[m * 3 + threadIdx.x];
    __syncthreads();

    int count = g_counts[m];
    int off = g_offsets[m];

    for (int base = chunk * TPB_MLP; base < count; base += K_CHUNKS * TPB_MLP) {
        int j = base + (int)threadIdx.x;
        if (j < count) {
            int r = g_rowids[off + j];
            float x6[IN_F];
#pragma unroll
            for (int k = 0; k < IN_F; k++) x6[k] = inputs[6 * r + k];

            // layer 0: 6 -> 64 (+relu)
            float2 h[32];
#pragma unroll
            for (int o = 0; o < 64; o += 2) {
                float acc0 = s[SB0 + o];
                float acc1 = s[SB0 + o + 1];
#pragma unroll
                for (int i = 0; i < IN_F; i++) {
                    acc0 = fmaf(s[SW0 + o * 6 + i], x6[i], acc0);
                    acc1 = fmaf(s[SW0 + (o + 1) * 6 + i], x6[i], acc1);
                }
                h[o >> 1] = make_float2(fmaxf(acc0, 0.f), fmaxf(acc1, 0.f));
            }

            // layers 1-3: 64 -> 64 (+relu)
            dense64(s + SW1, s + SB1, h);
            dense64(s + SW2, s + SB2, h);
            dense64(s + SW3, s + SB3, h);

            // layer 4: 64 -> 3 (no relu)
            float o3[OUT_F];
#pragma unroll
            for (int o = 0; o < OUT_F; o++) {
                const float4* wq = (const float4*)(s + SW4 + o * 64);
                float2 a = make_float2(0.f, 0.f), c = a;
#pragma unroll
                for (int i4 = 0; i4 < 16; i4++) {
                    float4 q = wq[i4];
                    a = ffma2(make_float2(q.x, q.y), h[2 * i4], a);
                    c = ffma2(make_float2(q.z, q.w), h[2 * i4 + 1], c);
                }
                o3[o] = s[SB4 + o] + (a.x + a.y) + (c.x + c.y);
            }
#pragma unroll
            for (int o = 0; o < OUT_F; o++) {
                out_model[3 * r + o] = o3[o];
                out_top[3 * r + o] = o3[o];
            }
        }
    }
}

// ---------------------------------------------------------------------
extern "C" void kernel_launch(void* const* d_in, const int* in_sizes, int n_in,
                              void* d_out, int out_size) {
    const float* inputs = (const float*)d_in[0];
    const float* w0 = (const float*)d_in[1];
    const float* b0 = (const float*)d_in[2];
    const float* w1 = (const float*)d_in[3];
    const float* b1 = (const float*)d_in[4];
    const float* w2 = (const float*)d_in[5];
    const float* b2 = (const float*)d_in[6];
    const float* w3 = (const float*)d_in[7];
    const float* b3 = (const float*)d_in[8];
    const float* w4 = (const float*)d_in[9];
    const float* b4 = (const float*)d_in[10];

    int B = in_sizes[0] / IN_F;
    if (B > B_MAX) B = B_MAX;
    float* out = (float*)d_out;

    // output layout: model(3B) | top(3B) | idx(B) | logits(64B) | probs(64B)
    size_t Bs = (size_t)B;
    float* out_model = out;
    float* out_top = out + 3 * Bs;
    float* out_idx = out + 6 * Bs;
    float* out_logits = out + 7 * Bs;
    float* out_probs = out + 71 * Bs;

    cudaFuncSetAttribute(k_mlp, cudaFuncAttributeMaxDynamicSharedMemorySize,
                         SMEM_BYTES);

    k_fill<<<1024, 256>>>(out_logits, out_probs, B * 16);
    k_index<<<256, 256>>>(inputs, out_idx, B);
    k_scan<<<1, 32>>>();
    k_scatter<<<256, 256>>>(B);
    k_mlp<<<NUM_MODELS * K_CHUNKS, TPB_MLP, SMEM_BYTES>>>(
        inputs, w0, b0, w1, b1, w2, b2, w3, b3, w4, b4, out_model, out_top);
}

// round 8
// speedup vs baseline: 1.7092x; 1.2984x over previous
#include <cuda_runtime.h>

#define NUM_MODELS 64
#define IN_F 6
#define HID 64
#define OUT_F 3
#define B_MAX 131072
#define K_CHUNKS 16
#define TPB_MLP 128

typedef unsigned long long u64;

// -------- scratch (no allocations allowed; __device__ globals) --------
__device__ int g_counts[NUM_MODELS];
__device__ int g_offsets[NUM_MODELS];
__device__ int g_reserve[NUM_MODELS];
__device__ int g_rowids[B_MAX];
__device__ unsigned char g_idx[B_MAX];

// -------- smem layout for one model's weights (floats) --------
#define SW0 0                    // 64*6
#define SB0 (SW0 + 384)          // 64
#define SW1 (SB0 + 64)           // 64*64  (offset 448 floats = 1792B, 16B aligned)
#define SB1 (SW1 + 4096)         // 64
#define SW2 (SB1 + 64)           // 64*64
#define SB2 (SW2 + 4096)         // 64
#define SW3 (SB2 + 64)           // 64*64
#define SB3 (SW3 + 4096)         // 64
#define SW4 (SB3 + 64)           // 3*64
#define SB4 (SW4 + 192)          // 3 (+1 pad)
#define SMEM_FLOATS (SB4 + 4)
#define SMEM_BYTES (SMEM_FLOATS * 4)

// ---- packed f32x2 kept in 64-bit registers end-to-end (no marshaling) ----
__device__ __forceinline__ u64 ffma2u(u64 a, u64 b, u64 c) {
    u64 d;
    asm("fma.rn.f32x2 %0, %1, %2, %3;" : "=l"(d) : "l"(a), "l"(b), "l"(c));
    return d;
}
__device__ __forceinline__ void unpack2(u64 v, float& lo, float& hi) {
    asm("mov.b64 {%0, %1}, %2;" : "=f"(lo), "=f"(hi) : "l"(v));
}
__device__ __forceinline__ u64 pack2(float lo, float hi) {
    u64 d;
    asm("mov.b64 %0, {%1, %2};" : "=l"(d) : "f"(lo), "f"(hi));
    return d;
}

// ---------------------------------------------------------------------
// Kernel 1: zero histogram/reservations + fill constant outputs
// ---------------------------------------------------------------------
__global__ void k_fill(float* __restrict__ out_logits,
                       float* __restrict__ out_probs, int n4) {
    if (blockIdx.x == 0 && threadIdx.x < NUM_MODELS) {
        g_counts[threadIdx.x] = 0;
        g_reserve[threadIdx.x] = 0;
    }
    int gid = blockIdx.x * blockDim.x + threadIdx.x;
    int stride = gridDim.x * blockDim.x;
    float4 ones = make_float4(1.f, 1.f, 1.f, 1.f);
    float4 prob = make_float4(0.015625f, 0.015625f, 0.015625f, 0.015625f);
    float4* L = (float4*)out_logits;
    float4* P = (float4*)out_probs;
    for (int i = gid; i < n4; i += stride) {
        L[i] = ones;
        P[i] = prob;
    }
}

// ---------------------------------------------------------------------
// Kernel 2: selection index per row; SMEM histogram -> 1 global atomic
// per (CTA, model). Correctly-rounded intrinsics (fast-math immune).
// ---------------------------------------------------------------------
__global__ void k_index(const float* __restrict__ in,
                        float* __restrict__ out_idx, int B) {
    __shared__ int hist[NUM_MODELS];
    if (threadIdx.x < NUM_MODELS) hist[threadIdx.x] = 0;
    __syncthreads();

    const float TWO_PI = 6.28318530717958647692f;
    int gid = blockIdx.x * blockDim.x + threadIdx.x;
    int stride = gridDim.x * blockDim.x;
    for (int r = gid; r < B; r += stride) {
        float x0 = in[6 * r + 0];
        float x2 = in[6 * r + 2];
        float ang = atan2f(x2, x0);
        float a = fmodf(__fadd_rn(ang, TWO_PI), TWO_PI);  // positive args: mod==fmod
        a = __fmul_rn(__fdiv_rn(a, TWO_PI), 64.0f);
        float f = floorf(a);
        int idx = (int)f;
        int idxw = idx > 63 ? 63 : (idx < 0 ? 0 : idx);   // XLA gather clamps OOB
        g_idx[r] = (unsigned char)idxw;
        out_idx[r] = f;                                   // selection_indices (as f32)
        atomicAdd(&hist[idxw], 1);
    }
    __syncthreads();
    if (threadIdx.x < NUM_MODELS) {
        int c = hist[threadIdx.x];
        if (c) atomicAdd(&g_counts[threadIdx.x], c);
    }
}

// ---------------------------------------------------------------------
// Kernel 3 (scan folded in): scatter rows into buckets. Each CTA scans
// g_counts locally; block 0 publishes g_offsets for k_mlp. Two-pass:
// count -> reserve global range (1 atomic per model per CTA) -> write.
// ---------------------------------------------------------------------
__global__ void k_scatter(int B) {
    __shared__ int hist[NUM_MODELS];
    __shared__ int sbase[NUM_MODELS];
    __shared__ int soff[NUM_MODELS];
    int per = (B + gridDim.x - 1) / gridDim.x;
    int r0 = blockIdx.x * per;
    int r1 = r0 + per;
    if (r1 > B) r1 = B;

    if (threadIdx.x < NUM_MODELS) {
        hist[threadIdx.x] = 0;
        soff[threadIdx.x] = g_counts[threadIdx.x];
    }
    __syncthreads();
    if (threadIdx.x == 0) {
        int run = 0;
        for (int m = 0; m < NUM_MODELS; m++) {
            int c = soff[m];
            soff[m] = run;
            run += c;
        }
    }
    __syncthreads();
    if (blockIdx.x == 0 && threadIdx.x < NUM_MODELS)
        g_offsets[threadIdx.x] = soff[threadIdx.x];

    for (int r = r0 + threadIdx.x; r < r1; r += blockDim.x)
        atomicAdd(&hist[g_idx[r]], 1);
    __syncthreads();
    if (threadIdx.x < NUM_MODELS) {
        int c = hist[threadIdx.x];
        sbase[threadIdx.x] =
            soff[threadIdx.x] + (c ? atomicAdd(&g_reserve[threadIdx.x], c) : 0);
        hist[threadIdx.x] = 0;
    }
    __syncthreads();
    for (int r = r0 + threadIdx.x; r < r1; r += blockDim.x) {
        int m = g_idx[r];
        g_rowids[sbase[m] + atomicAdd(&hist[m], 1)] = r;
    }
}

// ---------------------------------------------------------------------
// helpers for k_mlp
// ---------------------------------------------------------------------
__device__ __forceinline__ void cpyf4(float* dst, const float* src, int nf4) {
    const float4* s4 = (const float4*)src;
    float4* d4 = (float4*)dst;
    for (int i = threadIdx.x; i < nf4; i += TPB_MLP) d4[i] = s4[i];
}

// one 64x64 dense layer + relu. Activations/weights/accumulators stay in
// 64-bit registers (fma.rn.f32x2 on u64) -> zero pack/unpack in inner loop.
// unroll 4 bounds live ranges (~180 regs, no spill).
__device__ __forceinline__ void dense64u(const float* __restrict__ w,
                                         const float* __restrict__ b,
                                         u64 h[32]) {
    u64 hn[32];
#pragma unroll 4
    for (int o = 0; o < 64; o += 2) {
        const ulonglong2* w0q = (const ulonglong2*)(w + o * 64);
        const ulonglong2* w1q = (const ulonglong2*)(w + (o + 1) * 64);
        u64 a0 = 0, c0 = 0, a1 = 0, c1 = 0;
#pragma unroll
        for (int i4 = 0; i4 < 16; i4++) {
            ulonglong2 q0 = w0q[i4];
            ulonglong2 q1 = w1q[i4];
            a0 = ffma2u(q0.x, h[2 * i4], a0);
            c0 = ffma2u(q0.y, h[2 * i4 + 1], c0);
            a1 = ffma2u(q1.x, h[2 * i4], a1);
            c1 = ffma2u(q1.y, h[2 * i4 + 1], c1);
        }
        float a0l, a0h, c0l, c0h, a1l, a1h, c1l, c1h;
        unpack2(a0, a0l, a0h);
        unpack2(c0, c0l, c0h);
        unpack2(a1, a1l, a1h);
        unpack2(c1, c1l, c1h);
        float v0 = b[o] + (a0l + a0h) + (c0l + c0h);
        float v1 = b[o + 1] + (a1l + a1h) + (c1l + c1h);
        hn[o >> 1] = pack2(fmaxf(v0, 0.f), fmaxf(v1, 0.f));
    }
#pragma unroll
    for (int i = 0; i < 32; i++) h[i] = hn[i];
}

// ---------------------------------------------------------------------
// Kernel 4: bucketed MLP. blockIdx.x -> (model, chunk). One model per CTA,
// 52.5KB weights in dynamic smem. K_CHUNKS=16 -> 1024 CTAs, ~896 rows/SM
// makespan (vs 1024 at K=4/8).
// ---------------------------------------------------------------------
__global__ void __launch_bounds__(TPB_MLP)
k_mlp(const float* __restrict__ inputs,
      const float* __restrict__ w0, const float* __restrict__ b0,
      const float* __restrict__ w1, const float* __restrict__ b1,
      const float* __restrict__ w2, const float* __restrict__ b2,
      const float* __restrict__ w3, const float* __restrict__ b3,
      const float* __restrict__ w4, const float* __restrict__ b4,
      float* __restrict__ out_model, float* __restrict__ out_top) {
    extern __shared__ float s[];
    int m = blockIdx.x / K_CHUNKS;
    int chunk = blockIdx.x % K_CHUNKS;

    // cooperative weight load (all per-model slices are 16B-aligned)
    cpyf4(s + SW0, w0 + m * 384, 384 / 4);
    cpyf4(s + SB0, b0 + m * 64, 16);
    cpyf4(s + SW1, w1 + m * 4096, 1024);
    cpyf4(s + SB1, b1 + m * 64, 16);
    cpyf4(s + SW2, w2 + m * 4096, 1024);
    cpyf4(s + SB2, b2 + m * 64, 16);
    cpyf4(s + SW3, w3 + m * 4096, 1024);
    cpyf4(s + SB3, b3 + m * 64, 16);
    cpyf4(s + SW4, w4 + m * 192, 48);
    if (threadIdx.x < OUT_F) s[SB4 + threadIdx.x] = b4[m * 3 + threadIdx.x];
    __syncthreads();

    int count = g_counts[m];
    int off = g_offsets[m];

    for (int base = chunk * TPB_MLP; base < count; base += K_CHUNKS * TPB_MLP) {
        int j = base + (int)threadIdx.x;
        if (j < count) {
            int r = g_rowids[off + j];
            const float2* ip = (const float2*)(inputs + 6 * r);  // 8B aligned
            float2 p0 = ip[0], p1 = ip[1], p2 = ip[2];
            float x6[IN_F] = {p0.x, p0.y, p1.x, p1.y, p2.x, p2.y};

            // layer 0: 6 -> 64 (+relu), scalar (tiny)
            u64 h[32];
#pragma unroll
            for (int o = 0; o < 64; o += 2) {
                float acc0 = s[SB0 + o];
                float acc1 = s[SB0 + o + 1];
#pragma unroll
                for (int i = 0; i < IN_F; i++) {
                    acc0 = fmaf(s[SW0 + o * 6 + i], x6[i], acc0);
                    acc1 = fmaf(s[SW0 + (o + 1) * 6 + i], x6[i], acc1);
                }
                h[o >> 1] = pack2(fmaxf(acc0, 0.f), fmaxf(acc1, 0.f));
            }

            // layers 1-3: 64 -> 64 (+relu)
            dense64u(s + SW1, s + SB1, h);
            dense64u(s + SW2, s + SB2, h);
            dense64u(s + SW3, s + SB3, h);

            // layer 4: 64 -> 3 (no relu)
            float o3[OUT_F];
#pragma unroll
            for (int o = 0; o < OUT_F; o++) {
                const ulonglong2* wq = (const ulonglong2*)(s + SW4 + o * 64);
                u64 a = 0, c = 0;
#pragma unroll
                for (int i4 = 0; i4 < 16; i4++) {
                    ulonglong2 q = wq[i4];
                    a = ffma2u(q.x, h[2 * i4], a);
                    c = ffma2u(q.y, h[2 * i4 + 1], c);
                }
                float al, ah, cl, ch;
                unpack2(a, al, ah);
                unpack2(c, cl, ch);
                o3[o] = s[SB4 + o] + (al + ah) + (cl + ch);
            }
#pragma unroll
            for (int o = 0; o < OUT_F; o++) {
                out_model[3 * r + o] = o3[o];
                out_top[3 * r + o] = o3[o];
            }
        }
    }
}

// ---------------------------------------------------------------------
extern "C" void kernel_launch(void* const* d_in, const int* in_sizes, int n_in,
                              void* d_out, int out_size) {
    const float* inputs = (const float*)d_in[0];
    const float* w0 = (const float*)d_in[1];
    const float* b0 = (const float*)d_in[2];
    const float* w1 = (const float*)d_in[3];
    const float* b1 = (const float*)d_in[4];
    const float* w2 = (const float*)d_in[5];
    const float* b2 = (const float*)d_in[6];
    const float* w3 = (const float*)d_in[7];
    const float* b3 = (const float*)d_in[8];
    const float* w4 = (const float*)d_in[9];
    const float* b4 = (const float*)d_in[10];

    int B = in_sizes[0] / IN_F;
    if (B > B_MAX) B = B_MAX;
    float* out = (float*)d_out;

    // output layout: model(3B) | top(3B) | idx(B) | logits(64B) | probs(64B)
    size_t Bs = (size_t)B;
    float* out_model = out;
    float* out_top = out + 3 * Bs;
    float* out_idx = out + 6 * Bs;
    float* out_logits = out + 7 * Bs;
    float* out_probs = out + 71 * Bs;

    cudaFuncSetAttribute(k_mlp, cudaFuncAttributeMaxDynamicSharedMemorySize,
                         SMEM_BYTES);

    k_fill<<<1024, 256>>>(out_logits, out_probs, B * 16);
    k_index<<<256, 256>>>(inputs, out_idx, B);
    k_scatter<<<256, 256>>>(B);
    k_mlp<<<NUM_MODELS * K_CHUNKS, TPB_MLP, SMEM_BYTES>>>(
        inputs, w0, b0, w1, b1, w2, b2, w3, b3, w4, b4, out_model, out_top);
}

// round 10
// speedup vs baseline: 2.5260x; 1.4779x over previous
#include <cuda_runtime.h>

#define NUM_MODELS 64
#define IN_F 6
#define HID 64
#define OUT_F 3
#define B_MAX 131072
#define K_CHUNKS 4
#define TPB_MLP 128
#define RT 64      // rows per tile
#define WP 68      // padded weight row stride (transposed layout, conflict-free)

typedef unsigned long long u64;

// -------- scratch (no allocations allowed; __device__ globals) --------
__device__ int g_counts[NUM_MODELS];
__device__ int g_offsets[NUM_MODELS];
__device__ int g_reserve[NUM_MODELS];
__device__ int g_rowids[B_MAX];
__device__ unsigned char g_idx[B_MAX];

// -------- smem float offsets for k_mlp --------
#define OF_W0 0                       // 6*68 = 408 -> pad 416
#define OF_W1 416                     // 64*68 = 4352
#define OF_W2 4768
#define OF_W3 9120
#define OF_W4 13472                   // 3*68 = 204 -> pad to 13680
#define OF_B  13680                   // b0..b3 (64 each) + b4 (3) = 260 -> 13952
#define OF_A0 13952                   // 64*64 act ping
#define OF_A1 18048                   // 64*64 act pong
#define SMEM_FLOATS 22144
#define SMEM_BYTES (SMEM_FLOATS * 4)  // 88576 B -> 2 CTAs/SM

// ---- packed f32x2 kept in 64-bit registers end-to-end ----
__device__ __forceinline__ u64 ffma2u(u64 a, u64 b, u64 c) {
    u64 d;
    asm("fma.rn.f32x2 %0, %1, %2, %3;" : "=l"(d) : "l"(a), "l"(b), "l"(c));
    return d;
}
__device__ __forceinline__ void unpack2(u64 v, float& lo, float& hi) {
    asm("mov.b64 {%0, %1}, %2;" : "=f"(lo), "=f"(hi) : "l"(v));
}
__device__ __forceinline__ u64 pack2(float lo, float hi) {
    u64 d;
    asm("mov.b64 %0, {%1, %2};" : "=l"(d) : "f"(lo), "f"(hi));
    return d;
}

// ---------------------------------------------------------------------
// Kernel 1: zero histogram/reservations + fill constant outputs
// ---------------------------------------------------------------------
__global__ void k_fill(float* __restrict__ out_logits,
                       float* __restrict__ out_probs, int n4) {
    if (blockIdx.x == 0 && threadIdx.x < NUM_MODELS) {
        g_counts[threadIdx.x] = 0;
        g_reserve[threadIdx.x] = 0;
    }
    int gid = blockIdx.x * blockDim.x + threadIdx.x;
    int stride = gridDim.x * blockDim.x;
    float4 ones = make_float4(1.f, 1.f, 1.f, 1.f);
    float4 prob = make_float4(0.015625f, 0.015625f, 0.015625f, 0.015625f);
    float4* L = (float4*)out_logits;
    float4* P = (float4*)out_probs;
    for (int i = gid; i < n4; i += stride) {
        L[i] = ones;
        P[i] = prob;
    }
}

// ---------------------------------------------------------------------
// Kernel 2: selection index per row; SMEM histogram -> 1 global atomic
// per (CTA, model). Correctly-rounded intrinsics (fast-math immune).
// ---------------------------------------------------------------------
__global__ void k_index(const float* __restrict__ in,
                        float* __restrict__ out_idx, int B) {
    __shared__ int hist[NUM_MODELS];
    if (threadIdx.x < NUM_MODELS) hist[threadIdx.x] = 0;
    __syncthreads();

    const float TWO_PI = 6.28318530717958647692f;
    int gid = blockIdx.x * blockDim.x + threadIdx.x;
    int stride = gridDim.x * blockDim.x;
    for (int r = gid; r < B; r += stride) {
        float x0 = in[6 * r + 0];
        float x2 = in[6 * r + 2];
        float ang = atan2f(x2, x0);
        float a = fmodf(__fadd_rn(ang, TWO_PI), TWO_PI);  // positive args: mod==fmod
        a = __fmul_rn(__fdiv_rn(a, TWO_PI), 64.0f);
        float f = floorf(a);
        int idx = (int)f;
        int idxw = idx > 63 ? 63 : (idx < 0 ? 0 : idx);   // XLA gather clamps OOB
        g_idx[r] = (unsigned char)idxw;
        out_idx[r] = f;                                   // selection_indices (as f32)
        atomicAdd(&hist[idxw], 1);
    }
    __syncthreads();
    if (threadIdx.x < NUM_MODELS) {
        int c = hist[threadIdx.x];
        if (c) atomicAdd(&g_counts[threadIdx.x], c);
    }
}

// ---------------------------------------------------------------------
// Kernel 3: scatter rows into buckets (scan folded in; block 0 publishes
// g_offsets). Two-pass per CTA: count -> reserve range -> write.
// ---------------------------------------------------------------------
__global__ void k_scatter(int B) {
    __shared__ int hist[NUM_MODELS];
    __shared__ int sbase[NUM_MODELS];
    __shared__ int soff[NUM_MODELS];
    int per = (B + gridDim.x - 1) / gridDim.x;
    int r0 = blockIdx.x * per;
    int r1 = r0 + per;
    if (r1 > B) r1 = B;

    if (threadIdx.x < NUM_MODELS) {
        hist[threadIdx.x] = 0;
        soff[threadIdx.x] = g_counts[threadIdx.x];
    }
    __syncthreads();
    if (threadIdx.x == 0) {
        int run = 0;
        for (int m = 0; m < NUM_MODELS; m++) {
            int c = soff[m];
            soff[m] = run;
            run += c;
        }
    }
    __syncthreads();
    if (blockIdx.x == 0 && threadIdx.x < NUM_MODELS)
        g_offsets[threadIdx.x] = soff[threadIdx.x];

    for (int r = r0 + threadIdx.x; r < r1; r += blockDim.x)
        atomicAdd(&hist[g_idx[r]], 1);
    __syncthreads();
    if (threadIdx.x < NUM_MODELS) {
        int c = hist[threadIdx.x];
        sbase[threadIdx.x] =
            soff[threadIdx.x] + (c ? atomicAdd(&g_reserve[threadIdx.x], c) : 0);
        hist[threadIdx.x] = 0;
    }
    __syncthreads();
    for (int r = r0 + threadIdx.x; r < r1; r += blockDim.x) {
        int m = g_idx[r];
        g_rowids[sbase[m] + atomicAdd(&hist[m], 1)] = r;
    }
}

// ---------------------------------------------------------------------
// GEMM tile: 64 rows x 64 outs x K. Threads 16x8; each thread 4 rows x
// 8 outs, outputs packed as f32x2 pairs. Per k-step: 3 LDS.128 + 16 FFMA2
// (vs 2 FFMA2 per LDS before -> LDS traffic /10). Bias in acc init,
// relu at write-back to aOut[o][row].
// ---------------------------------------------------------------------
template <int K>
__device__ __forceinline__ void gemm_tile(const float* __restrict__ wT,
                                          const float* __restrict__ aIn,
                                          float* __restrict__ aOut,
                                          const float* __restrict__ bias,
                                          int tx, int ty) {
    u64 acc[4][4];
#pragma unroll
    for (int p = 0; p < 4; p++) {
        u64 bp = pack2(bias[ty * 8 + 2 * p], bias[ty * 8 + 2 * p + 1]);
        acc[0][p] = bp; acc[1][p] = bp; acc[2][p] = bp; acc[3][p] = bp;
    }
    const float* ap = aIn + tx * 4;
    const float* wp = wT + ty * 8;
#pragma unroll 4
    for (int k = 0; k < K; k++) {
        ulonglong2 aq = *(const ulonglong2*)(ap + k * RT);
        ulonglong2 wq0 = *(const ulonglong2*)(wp + k * WP);
        ulonglong2 wq1 = *(const ulonglong2*)(wp + k * WP + 4);
        float a0, a1, a2, a3;
        unpack2(aq.x, a0, a1);
        unpack2(aq.y, a2, a3);
        u64 dv[4] = {pack2(a0, a0), pack2(a1, a1), pack2(a2, a2), pack2(a3, a3)};
        u64 wv[4] = {wq0.x, wq0.y, wq1.x, wq1.y};
#pragma unroll
        for (int r = 0; r < 4; r++)
#pragma unroll
            for (int p = 0; p < 4; p++)
                acc[r][p] = ffma2u(wv[p], dv[r], acc[r][p]);
    }
#pragma unroll
    for (int r = 0; r < 4; r++) {
        int row = tx * 4 + r;
#pragma unroll
        for (int p = 0; p < 4; p++) {
            float v0, v1;
            unpack2(acc[r][p], v0, v1);
            int o = ty * 8 + 2 * p;
            aOut[o * RT + row] = fmaxf(v0, 0.f);
            aOut[(o + 1) * RT + row] = fmaxf(v1, 0.f);
        }
    }
}

// ---------------------------------------------------------------------
// Kernel 4: bucketed MLP as tiled GEMMs. One model per CTA; weights
// transposed into smem [k][out] (stride WP=68, conflict-free); act
// ping-pong [k][row] tiles of 64 rows. 2 CTAs/SM, grid 256 = one wave.
// ---------------------------------------------------------------------
__global__ void __launch_bounds__(TPB_MLP)
k_mlp(const float* __restrict__ inputs,
      const float* __restrict__ w0, const float* __restrict__ b0,
      const float* __restrict__ w1, const float* __restrict__ b1,
      const float* __restrict__ w2, const float* __restrict__ b2,
      const float* __restrict__ w3, const float* __restrict__ b3,
      const float* __restrict__ w4, const float* __restrict__ b4,
      float* __restrict__ out_model, float* __restrict__ out_top) {
    extern __shared__ float s[];
    int tid = threadIdx.x;
    int m = blockIdx.x / K_CHUNKS;
    int chunk = blockIdx.x % K_CHUNKS;
    int tx = tid & 15, ty = tid >> 4;

    // ---- stage weights (transposed) + biases ----
    {
        const float* srcs[3] = {w1 + m * 4096, w2 + m * 4096, w3 + m * 4096};
        float* dsts[3] = {s + OF_W1, s + OF_W2, s + OF_W3};
#pragma unroll
        for (int l = 0; l < 3; l++) {
            const float* src = srcs[l];
            float* dst = dsts[l];
            for (int idx = tid; idx < 4096; idx += TPB_MLP) {
                int o = idx >> 6, k = idx & 63;
                dst[k * WP + o] = src[idx];
            }
        }
        for (int idx = tid; idx < 384; idx += TPB_MLP) {
            int o = idx / 6, i = idx % 6;
            s[OF_W0 + i * WP + o] = w0[m * 384 + idx];
        }
        for (int idx = tid; idx < 192; idx += TPB_MLP) {
            int o = idx >> 6, k = idx & 63;
            s[OF_W4 + o * WP + k] = w4[m * 192 + idx];  // row-major, broadcast reads
        }
        if (tid < 64) {
            s[OF_B + tid] = b0[m * 64 + tid];
            s[OF_B + 64 + tid] = b1[m * 64 + tid];
            s[OF_B + 128 + tid] = b2[m * 64 + tid];
            s[OF_B + 192 + tid] = b3[m * 64 + tid];
        }
        if (tid < OUT_F) s[OF_B + 256 + tid] = b4[m * 3 + tid];
    }

    int count = g_counts[m];
    int off = g_offsets[m];

    for (int tb = chunk * RT; tb < count; tb += K_CHUNKS * RT) {
        int nrows = count - tb;
        if (nrows > RT) nrows = RT;
        __syncthreads();  // staging done / previous tile's readers of A0 done

        // gather input rows -> A0[k][row] (zeros for invalid rows)
        if (tid < RT) {
            float x[IN_F] = {0.f, 0.f, 0.f, 0.f, 0.f, 0.f};
            if (tid < nrows) {
                int rid = g_rowids[off + tb + tid];
                const float2* ip = (const float2*)(inputs + 6 * rid);
                float2 p0 = ip[0], p1 = ip[1], p2 = ip[2];
                x[0] = p0.x; x[1] = p0.y; x[2] = p1.x;
                x[3] = p1.y; x[4] = p2.x; x[5] = p2.y;
            }
#pragma unroll
            for (int i = 0; i < IN_F; i++) s[OF_A0 + i * RT + tid] = x[i];
        }
        __syncthreads();

        gemm_tile<6>(s + OF_W0, s + OF_A0, s + OF_A1, s + OF_B, tx, ty);
        __syncthreads();
        gemm_tile<64>(s + OF_W1, s + OF_A1, s + OF_A0, s + OF_B + 64, tx, ty);
        __syncthreads();
        gemm_tile<64>(s + OF_W2, s + OF_A0, s + OF_A1, s + OF_B + 128, tx, ty);
        __syncthreads();
        gemm_tile<64>(s + OF_W3, s + OF_A1, s + OF_A0, s + OF_B + 192, tx, ty);
        __syncthreads();

        // final layer 64 -> 3 from A0, scalar, one row per thread (tid<64)
        if (tid < RT) {
            float acc0 = s[OF_B + 256], acc1 = s[OF_B + 257], acc2 = s[OF_B + 258];
            const float* a = s + OF_A0 + tid;
            const float* wv = s + OF_W4;
#pragma unroll 8
            for (int k = 0; k < 64; k++) {
                float av = a[k * RT];
                acc0 = fmaf(wv[k], av, acc0);
                acc1 = fmaf(wv[WP + k], av, acc1);
                acc2 = fmaf(wv[2 * WP + k], av, acc2);
            }
            if (tid < nrows) {
                int rid = g_rowids[off + tb + tid];
                out_model[3 * rid + 0] = acc0;
                out_model[3 * rid + 1] = acc1;
                out_model[3 * rid + 2] = acc2;
                out_top[3 * rid + 0] = acc0;
                out_top[3 * rid + 1] = acc1;
                out_top[3 * rid + 2] = acc2;
            }
        }
    }
}

// ---------------------------------------------------------------------
extern "C" void kernel_launch(void* const* d_in, const int* in_sizes, int n_in,
                              void* d_out, int out_size) {
    const float* inputs = (const float*)d_in[0];
    const float* w0 = (const float*)d_in[1];
    const float* b0 = (const float*)d_in[2];
    const float* w1 = (const float*)d_in[3];
    const float* b1 = (const float*)d_in[4];
    const float* w2 = (const float*)d_in[5];
    const float* b2 = (const float*)d_in[6];
    const float* w3 = (const float*)d_in[7];
    const float* b3 = (const float*)d_in[8];
    const float* w4 = (const float*)d_in[9];
    const float* b4 = (const float*)d_in[10];

    int B = in_sizes[0] / IN_F;
    if (B > B_MAX) B = B_MAX;
    float* out = (float*)d_out;

    // output layout: model(3B) | top(3B) | idx(B) | logits(64B) | probs(64B)
    size_t Bs = (size_t)B;
    float* out_model = out;
    float* out_top = out + 3 * Bs;
    float* out_idx = out + 6 * Bs;
    float* out_logits = out + 7 * Bs;
    float* out_probs = out + 71 * Bs;

    cudaFuncSetAttribute(k_mlp, cudaFuncAttributeMaxDynamicSharedMemorySize,
                         SMEM_BYTES);

    k_fill<<<1024, 256>>>(out_logits, out_probs, B * 16);
    k_index<<<256, 256>>>(inputs, out_idx, B);
    k_scatter<<<256, 256>>>(B);
    k_mlp<<<NUM_MODELS * K_CHUNKS, TPB_MLP, SMEM_BYTES>>>(
        inputs, w0, b0, w1, b1, w2, b2, w3, b3, w4, b4, out_model, out_top);
}

// round 13
// speedup vs baseline: 2.6084x; 1.0326x over previous
#include <cuda_runtime.h>

#define NUM_MODELS 64
#define IN_F 6
#define HID 64
#define OUT_F 3
#define B_MAX 131072
#define K_CHUNKS 4
#define TPB_MLP 128
#define RT 64      // rows per tile
#define WP 68      // padded weight row stride (transposed layout, conflict-free)

typedef unsigned long long u64;

// -------- scratch (no allocations allowed; __device__ globals) --------
__device__ int g_counts[NUM_MODELS];
__device__ int g_offsets[NUM_MODELS];
__device__ int g_reserve[NUM_MODELS];
__device__ int g_rowids[B_MAX];
__device__ unsigned char g_idx[B_MAX];

// -------- smem float offsets for k_mlp --------
#define OF_W0 0                       // 6*68 = 408 -> pad 416
#define OF_W1 416                     // 64*68 = 4352
#define OF_W2 4768
#define OF_W3 9120
#define OF_W4 13472                   // 3*68 = 204 -> pad to 13680
#define OF_B  13680                   // b0..b3 (64 each) + b4 (3) = 260 -> 13952
#define OF_A0 13952                   // 64*64 act ping
#define OF_A1 18048                   // 64*64 act pong
#define SMEM_FLOATS 22144
#define SMEM_BYTES (SMEM_FLOATS * 4)  // 88576 B -> 2 CTAs/SM

// ---- packed f32x2 kept in 64-bit registers end-to-end ----
__device__ __forceinline__ u64 ffma2u(u64 a, u64 b, u64 c) {
    u64 d;
    asm("fma.rn.f32x2 %0, %1, %2, %3;" : "=l"(d) : "l"(a), "l"(b), "l"(c));
    return d;
}
__device__ __forceinline__ void unpack2(u64 v, float& lo, float& hi) {
    asm("mov.b64 {%0, %1}, %2;" : "=f"(lo), "=f"(hi) : "l"(v));
}
__device__ __forceinline__ u64 pack2(float lo, float hi) {
    u64 d;
    asm("mov.b64 %0, {%1, %2};" : "=l"(d) : "f"(lo), "f"(hi));
    return d;
}

// ---------------------------------------------------------------------
// Kernel 1: zero histogram/reservations + fill constant outputs
// ---------------------------------------------------------------------
__global__ void k_fill(float* __restrict__ out_logits,
                       float* __restrict__ out_probs, int n4) {
    if (blockIdx.x == 0 && threadIdx.x < NUM_MODELS) {
        g_counts[threadIdx.x] = 0;
        g_reserve[threadIdx.x] = 0;
    }
    int gid = blockIdx.x * blockDim.x + threadIdx.x;
    int stride = gridDim.x * blockDim.x;
    float4 ones = make_float4(1.f, 1.f, 1.f, 1.f);
    float4 prob = make_float4(0.015625f, 0.015625f, 0.015625f, 0.015625f);
    float4* L = (float4*)out_logits;
    float4* P = (float4*)out_probs;
    for (int i = gid; i < n4; i += stride) {
        L[i] = ones;
        P[i] = prob;
    }
}

// ---------------------------------------------------------------------
// Kernel 2: selection index per row; SMEM histogram -> 1 global atomic
// per (CTA, model). Correctly-rounded intrinsics (fast-math immune).
// ---------------------------------------------------------------------
__global__ void k_index(const float* __restrict__ in,
                        float* __restrict__ out_idx, int B) {
    __shared__ int hist[NUM_MODELS];
    if (threadIdx.x < NUM_MODELS) hist[threadIdx.x] = 0;
    __syncthreads();

    const float TWO_PI = 6.28318530717958647692f;
    int gid = blockIdx.x * blockDim.x + threadIdx.x;
    int stride = gridDim.x * blockDim.x;
    for (int r = gid; r < B; r += stride) {
        float x0 = in[6 * r + 0];
        float x2 = in[6 * r + 2];
        float ang = atan2f(x2, x0);
        float a = fmodf(__fadd_rn(ang, TWO_PI), TWO_PI);  // positive args: mod==fmod
        a = __fmul_rn(__fdiv_rn(a, TWO_PI), 64.0f);
        float f = floorf(a);
        int idx = (int)f;
        int idxw = idx > 63 ? 63 : (idx < 0 ? 0 : idx);   // XLA gather clamps OOB
        g_idx[r] = (unsigned char)idxw;
        out_idx[r] = f;                                   // selection_indices (as f32)
        atomicAdd(&hist[idxw], 1);
    }
    __syncthreads();
    if (threadIdx.x < NUM_MODELS) {
        int c = hist[threadIdx.x];
        if (c) atomicAdd(&g_counts[threadIdx.x], c);
    }
}

// ---------------------------------------------------------------------
// Kernel 3: scatter rows into buckets (scan folded in; block 0 publishes
// g_offsets). Two-pass per CTA: count -> reserve range -> write.
// ---------------------------------------------------------------------
__global__ void k_scatter(int B) {
    __shared__ int hist[NUM_MODELS];
    __shared__ int sbase[NUM_MODELS];
    __shared__ int soff[NUM_MODELS];
    int per = (B + gridDim.x - 1) / gridDim.x;
    int r0 = blockIdx.x * per;
    int r1 = r0 + per;
    if (r1 > B) r1 = B;

    if (threadIdx.x < NUM_MODELS) {
        hist[threadIdx.x] = 0;
        soff[threadIdx.x] = g_counts[threadIdx.x];
    }
    __syncthreads();
    if (threadIdx.x == 0) {
        int run = 0;
        for (int m = 0; m < NUM_MODELS; m++) {
            int c = soff[m];
            soff[m] = run;
            run += c;
        }
    }
    __syncthreads();
    if (blockIdx.x == 0 && threadIdx.x < NUM_MODELS)
        g_offsets[threadIdx.x] = soff[threadIdx.x];

    for (int r = r0 + threadIdx.x; r < r1; r += blockDim.x)
        atomicAdd(&hist[g_idx[r]], 1);
    __syncthreads();
    if (threadIdx.x < NUM_MODELS) {
        int c = hist[threadIdx.x];
        sbase[threadIdx.x] =
            soff[threadIdx.x] + (c ? atomicAdd(&g_reserve[threadIdx.x], c) : 0);
        hist[threadIdx.x] = 0;
    }
    __syncthreads();
    for (int r = r0 + threadIdx.x; r < r1; r += blockDim.x) {
        int m = g_idx[r];
        g_rowids[sbase[m] + atomicAdd(&hist[m], 1)] = r;
    }
}

// ---------------------------------------------------------------------
// GEMM tile: 64 rows x 64 outs x K; threads 16x8, thread tile 4 rows x
// 8 outs packed in f32x2. Explicit k+1 register prefetch (clamped index)
// hides the 29-cyc LDS latency behind the 16-FFMA2 burst -- R10 profile
// showed it exposed (fma=36%, issue=36% at 2 warps/SMSP).
// ---------------------------------------------------------------------
template <int K>
__device__ __forceinline__ void gemm_tile(const float* __restrict__ wT,
                                          const float* __restrict__ aIn,
                                          float* __restrict__ aOut,
                                          const float* __restrict__ bias,
                                          int tx, int ty) {
    u64 acc[4][4];
#pragma unroll
    for (int p = 0; p < 4; p++) {
        u64 bp = pack2(bias[ty * 8 + 2 * p], bias[ty * 8 + 2 * p + 1]);
        acc[0][p] = bp; acc[1][p] = bp; acc[2][p] = bp; acc[3][p] = bp;
    }
    const float* ap = aIn + tx * 4;
    const float* wp = wT + ty * 8;

    ulonglong2 aq = *(const ulonglong2*)(ap);
    ulonglong2 wq0 = *(const ulonglong2*)(wp);
    ulonglong2 wq1 = *(const ulonglong2*)(wp + 4);

#pragma unroll 4
    for (int k = 0; k < K; k++) {
        int kn = (k + 1 < K) ? (k + 1) : k;  // clamped prefetch (always valid)
        ulonglong2 aqn = *(const ulonglong2*)(ap + kn * RT);
        ulonglong2 wq0n = *(const ulonglong2*)(wp + kn * WP);
        ulonglong2 wq1n = *(const ulonglong2*)(wp + kn * WP + 4);

        float a0, a1, a2, a3;
        unpack2(aq.x, a0, a1);
        unpack2(aq.y, a2, a3);
        u64 dv[4] = {pack2(a0, a0), pack2(a1, a1), pack2(a2, a2), pack2(a3, a3)};
        u64 wv[4] = {wq0.x, wq0.y, wq1.x, wq1.y};
#pragma unroll
        for (int r = 0; r < 4; r++)
#pragma unroll
            for (int p = 0; p < 4; p++)
                acc[r][p] = ffma2u(wv[p], dv[r], acc[r][p]);

        aq = aqn; wq0 = wq0n; wq1 = wq1n;
    }
#pragma unroll
    for (int r = 0; r < 4; r++) {
        int row = tx * 4 + r;
#pragma unroll
        for (int p = 0; p < 4; p++) {
            float v0, v1;
            unpack2(acc[r][p], v0, v1);
            int o = ty * 8 + 2 * p;
            aOut[o * RT + row] = fmaxf(v0, 0.f);
            aOut[(o + 1) * RT + row] = fmaxf(v1, 0.f);
        }
    }
}

// ---------------------------------------------------------------------
// Kernel 4: bucketed MLP as tiled GEMMs. One model per CTA; weights
// transposed into smem [k][out] (stride WP=68, conflict-free); act
// ping-pong [k][row] tiles of 64 rows. 2 CTAs/SM, grid 256 = one wave.
// ---------------------------------------------------------------------
__global__ void __launch_bounds__(TPB_MLP)
k_mlp(const float* __restrict__ inputs,
      const float* __restrict__ w0, const float* __restrict__ b0,
      const float* __restrict__ w1, const float* __restrict__ b1,
      const float* __restrict__ w2, const float* __restrict__ b2,
      const float* __restrict__ w3, const float* __restrict__ b3,
      const float* __restrict__ w4, const float* __restrict__ b4,
      float* __restrict__ out_model, float* __restrict__ out_top) {
    extern __shared__ float s[];
    int tid = threadIdx.x;
    int m = blockIdx.x / K_CHUNKS;
    int chunk = blockIdx.x % K_CHUNKS;
    int tx = tid & 15, ty = tid >> 4;

    // ---- stage weights (transposed) + biases ----
    {
        const float* srcs[3] = {w1 + m * 4096, w2 + m * 4096, w3 + m * 4096};
        float* dsts[3] = {s + OF_W1, s + OF_W2, s + OF_W3};
#pragma unroll
        for (int l = 0; l < 3; l++) {
            const float* src = srcs[l];
            float* dst = dsts[l];
            for (int idx = tid; idx < 4096; idx += TPB_MLP) {
                int o = idx >> 6, k = idx & 63;
                dst[k * WP + o] = src[idx];
            }
        }
        for (int idx = tid; idx < 384; idx += TPB_MLP) {
            int o = idx / 6, i = idx % 6;
            s[OF_W0 + i * WP + o] = w0[m * 384 + idx];
        }
        for (int idx = tid; idx < 192; idx += TPB_MLP) {
            int o = idx >> 6, k = idx & 63;
            s[OF_W4 + o * WP + k] = w4[m * 192 + idx];  // row-major, broadcast reads
        }
        if (tid < 64) {
            s[OF_B + tid] = b0[m * 64 + tid];
            s[OF_B + 64 + tid] = b1[m * 64 + tid];
            s[OF_B + 128 + tid] = b2[m * 64 + tid];
            s[OF_B + 192 + tid] = b3[m * 64 + tid];
        }
        if (tid < OUT_F) s[OF_B + 256 + tid] = b4[m * 3 + tid];
    }

    int count = g_counts[m];
    int off = g_offsets[m];

    for (int tb = chunk * RT; tb < count; tb += K_CHUNKS * RT) {
        int nrows = count - tb;
        if (nrows > RT) nrows = RT;
        __syncthreads();  // staging done / previous tile's readers of A0 done

        // gather input rows -> A0[k][row] (zeros for invalid rows)
        if (tid < RT) {
            float x[IN_F] = {0.f, 0.f, 0.f, 0.f, 0.f, 0.f};
            if (tid < nrows) {
                int rid = g_rowids[off + tb + tid];
                const float2* ip = (const float2*)(inputs + 6 * rid);
                float2 p0 = ip[0], p1 = ip[1], p2 = ip[2];
                x[0] = p0.x; x[1] = p0.y; x[2] = p1.x;
                x[3] = p1.y; x[4] = p2.x; x[5] = p2.y;
            }
#pragma unroll
            for (int i = 0; i < IN_F; i++) s[OF_A0 + i * RT + tid] = x[i];
        }
        __syncthreads();

        gemm_tile<6>(s + OF_W0, s + OF_A0, s + OF_A1, s + OF_B, tx, ty);
        __syncthreads();
        gemm_tile<64>(s + OF_W1, s + OF_A1, s + OF_A0, s + OF_B + 64, tx, ty);
        __syncthreads();
        gemm_tile<64>(s + OF_W2, s + OF_A0, s + OF_A1, s + OF_B + 128, tx, ty);
        __syncthreads();
        gemm_tile<64>(s + OF_W3, s + OF_A1, s + OF_A0, s + OF_B + 192, tx, ty);
        __syncthreads();

        // final layer 64 -> 3 from A0, scalar, one row per thread (tid<64)
        if (tid < RT) {
            float acc0 = s[OF_B + 256], acc1 = s[OF_B + 257], acc2 = s[OF_B + 258];
            const float* a = s + OF_A0 + tid;
            const float* wv = s + OF_W4;
#pragma unroll 8
            for (int k = 0; k < 64; k++) {
                float av = a[k * RT];
                acc0 = fmaf(wv[k], av, acc0);
                acc1 = fmaf(wv[WP + k], av, acc1);
                acc2 = fmaf(wv[2 * WP + k], av, acc2);
            }
            if (tid < nrows) {
                int rid = g_rowids[off + tb + tid];
                out_model[3 * rid + 0] = acc0;
                out_model[3 * rid + 1] = acc1;
                out_model[3 * rid + 2] = acc2;
                out_top[3 * rid + 0] = acc0;
                out_top[3 * rid + 1] = acc1;
                out_top[3 * rid + 2] = acc2;
            }
        }
    }
}

// ---------------------------------------------------------------------
extern "C" void kernel_launch(void* const* d_in, const int* in_sizes, int n_in,
                              void* d_out, int out_size) {
    const float* inputs = (const float*)d_in[0];
    const float* w0 = (const float*)d_in[1];
    const float* b0 = (const float*)d_in[2];
    const float* w1 = (const float*)d_in[3];
    const float* b1 = (const float*)d_in[4];
    const float* w2 = (const float*)d_in[5];
    const float* b2 = (const float*)d_in[6];
    const float* w3 = (const float*)d_in[7];
    const float* b3 = (const float*)d_in[8];
    const float* w4 = (const float*)d_in[9];
    const float* b4 = (const float*)d_in[10];

    int B = in_sizes[0] / IN_F;
    if (B > B_MAX) B = B_MAX;
    float* out = (float*)d_out;

    // output layout: model(3B) | top(3B) | idx(B) | logits(64B) | probs(64B)
    size_t Bs = (size_t)B;
    float* out_model = out;
    float* out_top = out + 3 * Bs;
    float* out_idx = out + 6 * Bs;
    float* out_logits = out + 7 * Bs;
    float* out_probs = out + 71 * Bs;

    cudaFuncSetAttribute(k_mlp, cudaFuncAttributeMaxDynamicSharedMemorySize,
                         SMEM_BYTES);

    k_fill<<<1024, 256>>>(out_logits, out_probs, B * 16);
    k_index<<<256, 256>>>(inputs, out_idx, B);
    k_scatter<<<256, 256>>>(B);
    k_mlp<<<NUM_MODELS * K_CHUNKS, TPB_MLP, SMEM_BYTES>>>(
        inputs, w0, b0, w1, b1, w2, b2, w3, b3, w4, b4, out_model, out_top);
}